// round 8
// baseline (speedup 1.0000x reference)
#include <cuda_runtime.h>
#include <math.h>
#include <stdint.h>

#define NMAXN 200000
#define EMAXE 400000
#define GMAXG 8192
#define CMAX  256
#define SCAN_NB 1024

// ---------------- scratch (static device globals; no allocation) ----------------
__device__ float g_bufA[(size_t)NMAXN * CMAX];
__device__ float g_bufB[(size_t)NMAXN * CMAX];
__device__ float g_dis[NMAXN];
__device__ float g_selfn[NMAXN];
__device__ int   g_degi[NMAXN];
__device__ int   g_rowStart[NMAXN + 1];
__device__ int   g_blkSum[SCAN_NB];
__device__ int   g_fill[NMAXN];
__device__ int   g_csr_src[EMAXE];
__device__ float g_csr_w[EMAXE];
__device__ float g_pooled[(size_t)GMAXG * CMAX];
__device__ float g_stats[2 * CMAX];
__device__ float g_scale[CMAX];
__device__ float g_shift[CMAX];
__device__ float g_Wt2[128 * 256];
__device__ float g_Wt3[256 * 256];
__device__ float g_Wtp[256 * 256];

// ---------------- helpers ----------------
__device__ __forceinline__ uint32_t smem_u32(const void* p) {
    uint32_t a;
    asm("{ .reg .u64 t; cvta.to.shared.u64 t, %1; cvt.u32.u64 %0, t; }" : "=r"(a) : "l"(p));
    return a;
}
__device__ __forceinline__ float tf32r(float x) {
    uint32_t u;
    asm("cvt.rna.tf32.f32 %0, %1;" : "=r"(u) : "f"(x));
    return __uint_as_float(u);
}
__device__ __forceinline__ void mma_tf32(float d[4], const uint32_t a[4], const uint32_t b[2]) {
    asm volatile(
        "mma.sync.aligned.m16n8k8.row.col.f32.tf32.tf32.f32 "
        "{%0,%1,%2,%3}, {%4,%5,%6,%7}, {%8,%9}, {%0,%1,%2,%3};"
        : "+f"(d[0]), "+f"(d[1]), "+f"(d[2]), "+f"(d[3])
        : "r"(a[0]), "r"(a[1]), "r"(a[2]), "r"(a[3]), "r"(b[0]), "r"(b[1]));
}
__device__ __forceinline__ void cp_async8(uint32_t daddr, const void* gptr, uint32_t srcsz) {
    asm volatile("cp.async.ca.shared.global [%0], [%1], 8, %2;"
                 :: "r"(daddr), "l"(gptr), "r"(srcsz) : "memory");
}
#define CP_COMMIT() asm volatile("cp.async.commit_group;" ::: "memory")
#define CP_WAIT1()  asm volatile("cp.async.wait_group 1;" ::: "memory")
#define CP_WAIT0()  asm volatile("cp.async.wait_group 0;" ::: "memory")

// ---------------- prep ----------------
__global__ void k_zero_trans(const float* __restrict__ W2, const float* __restrict__ W3,
                             const float* __restrict__ Wp, int N) {
    int i = blockIdx.x * blockDim.x + threadIdx.x;
    if (i < N) { g_degi[i] = 0; g_fill[i] = 0; }
    if (i < 2 * CMAX) g_stats[i] = 0.f;
    if (i < 128 * 256) {
        int k = i / 256, n = i % 256;
        g_Wt2[(size_t)n * 128 + k] = tf32r(W2[i]);
    }
    if (i < 256 * 256) {
        int k = i / 256, n = i % 256;
        g_Wt3[(size_t)n * 256 + k] = tf32r(W3[i]);
        g_Wtp[(size_t)n * 256 + k] = tf32r(Wp[i]);
    }
}
__global__ void k_deg_accum(const int* __restrict__ dst, int E) {
    int e = blockIdx.x * blockDim.x + threadIdx.x;
    if (e < E) atomicAdd(&g_degi[dst[e]], 1);
}
// scan level 1 + dis/selfn computation (degree is final here)
__global__ void k_scan1(int N) {
    __shared__ int sh[256];
    int i = blockIdx.x * 256 + threadIdx.x;
    int v = (i < N) ? g_degi[i] : 0;
    if (i < N) {
        float d = (float)(v + 1);
        g_dis[i] = rsqrtf(d);
        g_selfn[i] = 1.0f / d;
    }
    sh[threadIdx.x] = v;
    __syncthreads();
    for (int off = 1; off < 256; off <<= 1) {
        int t = (threadIdx.x >= off) ? sh[threadIdx.x - off] : 0;
        __syncthreads();
        sh[threadIdx.x] += t;
        __syncthreads();
    }
    if (i < N) g_rowStart[i] = sh[threadIdx.x] - v;
    if (threadIdx.x == 255) g_blkSum[blockIdx.x] = sh[255];
}
__global__ void k_scan2(int NB) {
    __shared__ int sh[SCAN_NB];
    int v = ((int)threadIdx.x < NB) ? g_blkSum[threadIdx.x] : 0;
    sh[threadIdx.x] = v;
    __syncthreads();
    for (int off = 1; off < SCAN_NB; off <<= 1) {
        int t = ((int)threadIdx.x >= off) ? sh[threadIdx.x - off] : 0;
        __syncthreads();
        sh[threadIdx.x] += t;
        __syncthreads();
    }
    if ((int)threadIdx.x < NB) g_blkSum[threadIdx.x] = sh[threadIdx.x] - v;
}
__global__ void k_scan3(int N, int E) {
    int i = blockIdx.x * blockDim.x + threadIdx.x;
    if (i < N) g_rowStart[i] += g_blkSum[i >> 8];
    if (i == 0) g_rowStart[N] = E;
}
__global__ void k_csr_fill(const int* __restrict__ src, const int* __restrict__ dst, int E) {
    int e = blockIdx.x * blockDim.x + threadIdx.x;
    if (e < E) {
        int s = src[e], d = dst[e];
        int pos = g_rowStart[d] + atomicAdd(&g_fill[d], 1);
        g_csr_src[pos] = s;
        g_csr_w[pos]   = g_dis[s] * g_dis[d];
    }
}

// ---------------- fused layer-1: gather9 + GEMM[9->128] + stats ----------------
__global__ __launch_bounds__(256) void k_layer1(const float* __restrict__ x,
                                                const float* __restrict__ W1,
                                                float* __restrict__ Y, int N) {
    __shared__ float Ws[9 * 128];
    __shared__ float sstat[256];
    int tid = threadIdx.x;
    for (int i = tid; i < 9 * 128; i += 256) Ws[i] = W1[i];
    sstat[tid] = 0.f;
    __syncthreads();
    int wid = tid >> 5, lane = tid & 31;
    int i = blockIdx.x * 8 + wid;
    if (i < N) {
        float acc = 0.f;
        if (lane < 9) acc = g_selfn[i] * x[(size_t)i * 9 + lane];
        int st = g_rowStart[i], en = g_rowStart[i + 1];
        for (int j = st; j < en; j++) {
            int s = g_csr_src[j];
            float w = g_csr_w[j];
            if (lane < 9) acc += w * x[(size_t)s * 9 + lane];
        }
        float a[9];
#pragma unroll
        for (int k = 0; k < 9; k++) a[k] = __shfl_sync(0xFFFFFFFF, acc, k);
#pragma unroll
        for (int q = 0; q < 4; q++) {
            int c = q * 32 + lane;
            float y = 0.f;
#pragma unroll
            for (int k = 0; k < 9; k++) y += a[k] * Ws[k * 128 + c];
            Y[(size_t)i * 128 + c] = y;
            atomicAdd(&sstat[c], y);
            atomicAdd(&sstat[128 + c], y * y);
        }
    }
    __syncthreads();
    if (tid < 128) {
        atomicAdd(&g_stats[tid], sstat[tid]);
        atomicAdd(&g_stats[256 + tid], sstat[128 + tid]);
    }
}

// ---------------- BN finalize (resets stats for next layer) ----------------
__global__ void k_finalize(const float* __restrict__ gamma,
                           const float* __restrict__ beta, int N, int C) {
    int c = threadIdx.x;
    if (c < C) {
        float invN = 1.0f / (float)N;
        float mean = g_stats[c] * invN;
        float var  = g_stats[256 + c] * invN - mean * mean;
        float sc   = gamma[c] * rsqrtf(var + 1e-5f);
        g_scale[c] = sc;
        g_shift[c] = beta[c] - mean * sc;
        g_stats[c] = 0.f;
        g_stats[256 + c] = 0.f;
    }
}

// ---------------- fused gather+BN+ReLU + tf32 GEMM + stats ----------------
// Yout[N,256] = ( A_hat * bnrelu(Yin) )[128-row tile] @ Wt^T; Wt [256,K] tf32.
// CTA: 128 rows x 256 cols, 512 threads, 16 warps (warp tile 64x32).
// A-tile built per 32-k slice by gathering (4 threads/row, 8ch each).
template <int K>
__global__ __launch_bounds__(512, 1) void k_mma_g(const float* __restrict__ Yin,
                                                  const float* __restrict__ Wt,
                                                  float* __restrict__ Yout, int M) {
    extern __shared__ __align__(16) float sm[];
    // layout: A[2][128*36] | B[2][256*36] | sc[K] | sh[K]
    constexpr int ASZ = 128 * 36, BSZ = 256 * 36;
    constexpr int NPRE = 6;
    float* s_sc = sm + 2 * ASZ + 2 * BSZ;
    float* s_sh = s_sc + K;
    const uint32_t sbase = smem_u32(sm);
    const int tid  = threadIdx.x;
    const int wid  = tid >> 5;
    const int lane = tid & 31;
    const int wr   = (wid & 1) * 64;
    const int wc   = (wid >> 1) * 32;
    const int row0 = blockIdx.x * 128;
    const int fgq  = lane >> 2;          // mma group id
    const int ftq  = lane & 3;
    const int nk   = K / 32;

    // gather ownership: 4 threads per row, 8 channels each
    const int grow = tid >> 2;
    const int gq   = tid & 3;
    const int gi   = row0 + grow;
    int st = 0, en = 0;
    float selfw = 0.f;
    if (gi < M) { st = g_rowStart[gi]; en = g_rowStart[gi + 1]; selfw = g_selfn[gi]; }
    const int degc = en - st;
    int   sl[NPRE];
    float wl[NPRE];
#pragma unroll
    for (int t = 0; t < NPRE; t++) {
        if (t < degc) { sl[t] = g_csr_src[st + t]; wl[t] = g_csr_w[st + t]; }
        else          { sl[t] = 0; wl[t] = 0.f; }
    }
    for (int i = tid; i < K; i += 512) { s_sc[i] = g_scale[i]; s_sh[i] = g_shift[i]; }

    float acc[4][4][4];
#pragma unroll
    for (int mt = 0; mt < 4; mt++)
#pragma unroll
        for (int nt = 0; nt < 4; nt++)
#pragma unroll
            for (int q = 0; q < 4; q++) acc[mt][nt][q] = 0.f;

    const float4* Yv = (const float4*)Yin;

    auto do_gather = [&](int kt, int buf) {
        const int k0 = kt * 32;
        const int koff = (k0 >> 2) + gq * 2;
        float4 sc0 = *(const float4*)&s_sc[k0 + gq * 8];
        float4 sc1 = *(const float4*)&s_sc[k0 + gq * 8 + 4];
        float4 sh0 = *(const float4*)&s_sh[k0 + gq * 8];
        float4 sh1 = *(const float4*)&s_sh[k0 + gq * 8 + 4];
        float4 a0 = make_float4(0.f, 0.f, 0.f, 0.f), a1 = a0;
        // self
        {
            float4 v0 = make_float4(0.f, 0.f, 0.f, 0.f), v1 = v0;
            if (gi < M) {
                v0 = Yv[(size_t)gi * (K / 4) + koff];
                v1 = Yv[(size_t)gi * (K / 4) + koff + 1];
            }
            a0.x += selfw * fmaxf(0.f, v0.x * sc0.x + sh0.x);
            a0.y += selfw * fmaxf(0.f, v0.y * sc0.y + sh0.y);
            a0.z += selfw * fmaxf(0.f, v0.z * sc0.z + sh0.z);
            a0.w += selfw * fmaxf(0.f, v0.w * sc0.w + sh0.w);
            a1.x += selfw * fmaxf(0.f, v1.x * sc1.x + sh1.x);
            a1.y += selfw * fmaxf(0.f, v1.y * sc1.y + sh1.y);
            a1.z += selfw * fmaxf(0.f, v1.z * sc1.z + sh1.z);
            a1.w += selfw * fmaxf(0.f, v1.w * sc1.w + sh1.w);
        }
#pragma unroll
        for (int t = 0; t < NPRE; t++) {
            float4 v0 = make_float4(0.f, 0.f, 0.f, 0.f), v1 = v0;
            float w = wl[t];
            if (t < degc) {
                v0 = Yv[(size_t)sl[t] * (K / 4) + koff];
                v1 = Yv[(size_t)sl[t] * (K / 4) + koff + 1];
            }
            a0.x += w * fmaxf(0.f, v0.x * sc0.x + sh0.x);
            a0.y += w * fmaxf(0.f, v0.y * sc0.y + sh0.y);
            a0.z += w * fmaxf(0.f, v0.z * sc0.z + sh0.z);
            a0.w += w * fmaxf(0.f, v0.w * sc0.w + sh0.w);
            a1.x += w * fmaxf(0.f, v1.x * sc1.x + sh1.x);
            a1.y += w * fmaxf(0.f, v1.y * sc1.y + sh1.y);
            a1.z += w * fmaxf(0.f, v1.z * sc1.z + sh1.z);
            a1.w += w * fmaxf(0.f, v1.w * sc1.w + sh1.w);
        }
        for (int j = st + NPRE; j < en; j++) {
            int s = g_csr_src[j];
            float w = g_csr_w[j];
            float4 v0 = Yv[(size_t)s * (K / 4) + koff];
            float4 v1 = Yv[(size_t)s * (K / 4) + koff + 1];
            a0.x += w * fmaxf(0.f, v0.x * sc0.x + sh0.x);
            a0.y += w * fmaxf(0.f, v0.y * sc0.y + sh0.y);
            a0.z += w * fmaxf(0.f, v0.z * sc0.z + sh0.z);
            a0.w += w * fmaxf(0.f, v0.w * sc0.w + sh0.w);
            a1.x += w * fmaxf(0.f, v1.x * sc1.x + sh1.x);
            a1.y += w * fmaxf(0.f, v1.y * sc1.y + sh1.y);
            a1.z += w * fmaxf(0.f, v1.z * sc1.z + sh1.z);
            a1.w += w * fmaxf(0.f, v1.w * sc1.w + sh1.w);
        }
        uint32_t da = sbase + (uint32_t)(buf * ASZ + grow * 36 + gq * 8) * 4;
        float x0 = tf32r(a0.x), x1 = tf32r(a0.y), x2 = tf32r(a0.z), x3 = tf32r(a0.w);
        float x4 = tf32r(a1.x), x5 = tf32r(a1.y), x6 = tf32r(a1.z), x7 = tf32r(a1.w);
        asm volatile("st.shared.v4.b32 [%0], {%1,%2,%3,%4};"
                     :: "r"(da), "f"(x0), "f"(x1), "f"(x2), "f"(x3) : "memory");
        asm volatile("st.shared.v4.b32 [%0], {%1,%2,%3,%4};"
                     :: "r"(da + 16), "f"(x4), "f"(x5), "f"(x6), "f"(x7) : "memory");
    };

    auto load_B = [&](int buf, int k0) {
#pragma unroll
        for (int i = 0; i < 8; i++) {
            int idx = tid + i * 512;
            int n = idx >> 4, j2 = idx & 15;
            uint32_t db = sbase + (uint32_t)(2 * ASZ + buf * BSZ + n * 36 + j2 * 2) * 4;
            cp_async8(db, Wt + (size_t)n * K + k0 + j2 * 2, 8u);
        }
    };

    __syncthreads();          // s_sc/s_sh ready (needed by do_gather)
    do_gather(0, 0);
    load_B(0, 0);
    CP_COMMIT();
    if (nk > 1) { load_B(1, 32); CP_COMMIT(); }
    if (nk > 1) CP_WAIT1(); else CP_WAIT0();
    __syncthreads();

    for (int kt = 0; kt < nk; kt++) {
        const float* As = sm + (kt & 1) * ASZ;
        const float* Bs = sm + 2 * ASZ + (kt & 1) * BSZ;
#pragma unroll
        for (int kk = 0; kk < 4; kk++) {
            uint32_t af[4][4], bf[4][2];
#pragma unroll
            for (int mt = 0; mt < 4; mt++) {
                int r = wr + mt * 16 + fgq;
                af[mt][0] = __float_as_uint(As[r * 36 + kk * 8 + ftq]);
                af[mt][1] = __float_as_uint(As[(r + 8) * 36 + kk * 8 + ftq]);
                af[mt][2] = __float_as_uint(As[r * 36 + kk * 8 + 4 + ftq]);
                af[mt][3] = __float_as_uint(As[(r + 8) * 36 + kk * 8 + 4 + ftq]);
            }
#pragma unroll
            for (int nt = 0; nt < 4; nt++) {
                int n = wc + nt * 8 + fgq;
                bf[nt][0] = __float_as_uint(Bs[n * 36 + kk * 8 + ftq]);
                bf[nt][1] = __float_as_uint(Bs[n * 36 + kk * 8 + 4 + ftq]);
            }
#pragma unroll
            for (int mt = 0; mt < 4; mt++)
#pragma unroll
                for (int nt = 0; nt < 4; nt++)
                    mma_tf32(acc[mt][nt], af[mt], bf[nt]);
        }
        if (kt + 1 < nk) {
            do_gather(kt + 1, (kt + 1) & 1);
            if (kt + 2 < nk) { load_B((kt + 2) & 1, (kt + 2) * 32); CP_COMMIT(); CP_WAIT1(); }
            else             { CP_WAIT0(); }
            __syncthreads();
        }
    }

    // ---- epilogue: write Yout + stats ----
#pragma unroll
    for (int mt = 0; mt < 4; mt++) {
        int r0 = row0 + wr + mt * 16 + fgq;
        int r1 = r0 + 8;
#pragma unroll
        for (int nt = 0; nt < 4; nt++) {
            int c = wc + nt * 8 + ftq * 2;
            if (r0 < M)
                *(float2*)(Yout + (size_t)r0 * 256 + c) =
                    make_float2(acc[mt][nt][0], acc[mt][nt][1]);
            if (r1 < M)
                *(float2*)(Yout + (size_t)r1 * 256 + c) =
                    make_float2(acc[mt][nt][2], acc[mt][nt][3]);
        }
    }
#pragma unroll
    for (int nt = 0; nt < 4; nt++) {
#pragma unroll
        for (int q = 0; q < 2; q++) {
            float s = 0.f, sq = 0.f;
#pragma unroll
            for (int mt = 0; mt < 4; mt++) {
                float a = acc[mt][nt][q], b = acc[mt][nt][q + 2];
                s += a + b;
                sq += a * a + b * b;
            }
#pragma unroll
            for (int off = 4; off < 32; off <<= 1) {
                s  += __shfl_xor_sync(0xFFFFFFFF, s, off);
                sq += __shfl_xor_sync(0xFFFFFFFF, sq, off);
            }
            if (fgq == 0) {
                int c = wc + nt * 8 + ftq * 2 + q;
                atomicAdd(&g_stats[c], s);
                atomicAdd(&g_stats[256 + c], sq);
            }
        }
    }
}

// ---------------- dense tf32 mma GEMM (final linear), cp.async A ----------------
__global__ __launch_bounds__(256, 2) void k_mma(const float* __restrict__ A,
                                                const float* __restrict__ Wt,
                                                float* __restrict__ C,
                                                int M, int K,
                                                const float* __restrict__ bias) {
    extern __shared__ __align__(16) float sm[];
    const int tid  = threadIdx.x;
    const int wid  = tid >> 5;
    const int lane = tid & 31;
    const int wr   = (wid & 1) * 64;
    const int wc   = (wid >> 1) * 32;
    const int row0 = blockIdx.y * 128;
    const int col0 = blockIdx.x * 128;
    const int gq   = lane >> 2;
    const int tq   = lane & 3;
    const uint32_t sbase = smem_u32(sm);
    const int nk = K >> 5;

    float acc[4][4][4];
#pragma unroll
    for (int mt = 0; mt < 4; mt++)
#pragma unroll
        for (int nt = 0; nt < 4; nt++)
#pragma unroll
            for (int q = 0; q < 4; q++) acc[mt][nt][q] = 0.f;

    auto load_stage = [&](int s, int k0) {
#pragma unroll
        for (int i = 0; i < 8; i++) {
            int idx = tid + i * 256;
            int r = idx >> 4, j2 = idx & 15;
            int gr = row0 + r;
            uint32_t da = sbase + (uint32_t)(s * 4608 + r * 36 + j2 * 2) * 4;
            cp_async8(da, A + (size_t)gr * K + k0 + j2 * 2, (gr < M) ? 8u : 0u);
        }
#pragma unroll
        for (int i = 0; i < 8; i++) {
            int idx = tid + i * 256;
            int n = idx >> 4, j2 = idx & 15;
            uint32_t db = sbase + (uint32_t)(9216 + s * 4608 + n * 36 + j2 * 2) * 4;
            cp_async8(db, Wt + (size_t)(col0 + n) * K + k0 + j2 * 2, 8u);
        }
    };

    load_stage(0, 0);
    CP_COMMIT();
    for (int kt = 0; kt < nk; kt++) {
        if (kt + 1 < nk) load_stage((kt + 1) & 1, (kt + 1) * 32);
        CP_COMMIT();
        CP_WAIT1();
        __syncthreads();
        const float* As = sm + (kt & 1) * 4608;
        const float* Bs = sm + 9216 + (kt & 1) * 4608;
#pragma unroll
        for (int kk = 0; kk < 4; kk++) {
            uint32_t af[4][4], bf[4][2];
#pragma unroll
            for (int mt = 0; mt < 4; mt++) {
                int r = wr + mt * 16 + gq;
                af[mt][0] = __float_as_uint(As[r * 36 + kk * 8 + tq]);
                af[mt][1] = __float_as_uint(As[(r + 8) * 36 + kk * 8 + tq]);
                af[mt][2] = __float_as_uint(As[r * 36 + kk * 8 + 4 + tq]);
                af[mt][3] = __float_as_uint(As[(r + 8) * 36 + kk * 8 + 4 + tq]);
            }
#pragma unroll
            for (int nt = 0; nt < 4; nt++) {
                int n = wc + nt * 8 + gq;
                bf[nt][0] = __float_as_uint(Bs[n * 36 + kk * 8 + tq]);
                bf[nt][1] = __float_as_uint(Bs[n * 36 + kk * 8 + 4 + tq]);
            }
#pragma unroll
            for (int mt = 0; mt < 4; mt++)
#pragma unroll
                for (int nt = 0; nt < 4; nt++)
                    mma_tf32(acc[mt][nt], af[mt], bf[nt]);
        }
        __syncthreads();
    }

#pragma unroll
    for (int mt = 0; mt < 4; mt++) {
        int r0 = row0 + wr + mt * 16 + gq;
        int r1 = r0 + 8;
#pragma unroll
        for (int nt = 0; nt < 4; nt++) {
            int c = col0 + wc + nt * 8 + tq * 2;
            float b0 = bias ? bias[c] : 0.f;
            float b1 = bias ? bias[c + 1] : 0.f;
            if (r0 < M)
                *(float2*)(C + (size_t)r0 * 256 + c) =
                    make_float2(acc[mt][nt][0] + b0, acc[mt][nt][1] + b1);
            if (r1 < M)
                *(float2*)(C + (size_t)r1 * 256 + c) =
                    make_float2(acc[mt][nt][2] + b0, acc[mt][nt][3] + b1);
        }
    }
}

// ---------------- pool with fused BN+ReLU (batch sorted) ----------------
__global__ void k_pool(const float* __restrict__ Y, const int* __restrict__ batch,
                       int N, int G) {
    int g = blockIdx.x;
    int c = threadIdx.x;
    __shared__ int s_lo, s_hi;
    if (c == 0) {
        int lo = 0, hi = N;
        while (lo < hi) { int m = (lo + hi) >> 1; if (batch[m] < g) lo = m + 1; else hi = m; }
        s_lo = lo;
        int lo2 = lo, hi2 = N;
        while (lo2 < hi2) { int m = (lo2 + hi2) >> 1; if (batch[m] <= g) lo2 = m + 1; else hi2 = m; }
        s_hi = lo2;
    }
    __syncthreads();
    float sc = g_scale[c], sh = g_shift[c];
    float sum = 0.f;
    for (int i = s_lo; i < s_hi; i++)
        sum += fmaxf(0.f, Y[(size_t)i * 256 + c] * sc + sh);
    int cnt = s_hi - s_lo;
    g_pooled[(size_t)g * 256 + c] = tf32r(sum / fmaxf((float)cnt, 1.0f));
}

// ---------------- host launcher ----------------
extern "C" void kernel_launch(void* const* d_in, const int* in_sizes, int n_in,
                              void* d_out, int out_size) {
    const float* x     = (const float*)d_in[0];
    const int*   ei    = (const int*)d_in[1];
    const int*   batch = (const int*)d_in[2];
    const float* W1  = (const float*)d_in[4];
    const float* g1  = (const float*)d_in[6];
    const float* be1 = (const float*)d_in[7];
    const float* W2  = (const float*)d_in[8];
    const float* g2  = (const float*)d_in[10];
    const float* be2 = (const float*)d_in[11];
    const float* W3  = (const float*)d_in[12];
    const float* g3  = (const float*)d_in[14];
    const float* be3 = (const float*)d_in[15];
    const float* Wp  = (const float*)d_in[16];
    const float* bp  = (const float*)d_in[17];
    float* out = (float*)d_out;

    const int N = in_sizes[0] / 9;
    const int E = in_sizes[1] / 2;
    const int G = out_size / 256;
    const int NB = (N + 255) / 256;
    const int SMEM_MMA  = 4 * 4608 * 4;                              // dense k_mma
    const int SMEM_MMAG = (2 * 128 * 36 + 2 * 256 * 36 + 2 * 256) * 4; // 112640

    cudaFuncSetAttribute(k_mma, cudaFuncAttributeMaxDynamicSharedMemorySize, SMEM_MMA);
    cudaFuncSetAttribute(k_mma_g<128>, cudaFuncAttributeMaxDynamicSharedMemorySize, SMEM_MMAG);
    cudaFuncSetAttribute(k_mma_g<256>, cudaFuncAttributeMaxDynamicSharedMemorySize, SMEM_MMAG);

    void *pA, *pB, *pPooled, *pWt2, *pWt3, *pWtp;
    cudaGetSymbolAddress(&pA, g_bufA);
    cudaGetSymbolAddress(&pB, g_bufB);
    cudaGetSymbolAddress(&pPooled, g_pooled);
    cudaGetSymbolAddress(&pWt2, g_Wt2);
    cudaGetSymbolAddress(&pWt3, g_Wt3);
    cudaGetSymbolAddress(&pWtp, g_Wtp);
    float* bufA = (float*)pA;
    float* bufB = (float*)pB;

    const int* src = ei;
    const int* dst = ei + E;

    // ---- prep ----
    k_zero_trans<<<NB, 256>>>(W2, W3, Wp, N);
    k_deg_accum<<<(E + 255) / 256, 256>>>(dst, E);
    k_scan1<<<NB, 256>>>(N);
    k_scan2<<<1, SCAN_NB>>>(NB);
    k_scan3<<<NB, 256>>>(N, E);
    k_csr_fill<<<(E + 255) / 256, 256>>>(src, dst, E);

    const int tiles = (N + 127) / 128;

    // ---- Layer 1: gather9 + GEMM + stats -> Y1 in bufA ----
    k_layer1<<<(N + 7) / 8, 256>>>(x, W1, bufA, N);
    k_finalize<<<1, 128>>>(g1, be1, N, 128);

    // ---- Layer 2: fused gather(Y1)+GEMM -> Y2 in bufB ----
    k_mma_g<128><<<tiles, 512, SMEM_MMAG>>>(bufA, (const float*)pWt2, bufB, N);
    k_finalize<<<1, 256>>>(g2, be2, N, 256);

    // ---- Layer 3: fused gather(Y2)+GEMM -> Y3 in bufA ----
    k_mma_g<256><<<tiles, 512, SMEM_MMAG>>>(bufB, (const float*)pWt3, bufA, N);
    k_finalize<<<1, 256>>>(g3, be3, N, 256);

    // ---- pool (fused BN3+ReLU) + final linear ----
    k_pool<<<G, 256>>>(bufA, batch, N, G);
    {
        dim3 grid(2, (G + 127) / 128);
        k_mma<<<grid, 256, SMEM_MMA>>>((const float*)pPooled, (const float*)pWtp, out,
                                       G, 256, bp);
    }
}

// round 9
// speedup vs baseline: 1.1982x; 1.1982x over previous
#include <cuda_runtime.h>
#include <math.h>
#include <stdint.h>

#define NMAXN 200000
#define EMAXE 400000
#define GMAXG 8192
#define CMAX  256
#define SCAN_NB 1024

// ---------------- scratch (static device globals; no allocation) ----------------
__device__ float g_bufA[(size_t)NMAXN * CMAX];
__device__ float g_bufB[(size_t)NMAXN * CMAX];
__device__ float g_dis[NMAXN];
__device__ float g_selfn[NMAXN];
__device__ int   g_degi[NMAXN];
__device__ int   g_rowStart[NMAXN + 1];
__device__ int   g_blkSum[SCAN_NB];
__device__ int   g_fill[NMAXN];
__device__ int   g_csr_src[EMAXE];
__device__ float g_csr_w[EMAXE];
__device__ float g_pooled[(size_t)GMAXG * CMAX];
__device__ float g_stats[2 * CMAX];
__device__ float g_scale[CMAX];
__device__ float g_shift[CMAX];
__device__ float g_Wt2[128 * 256];
__device__ float g_Wt3[256 * 256];
__device__ float g_Wtp[256 * 256];

// ---------------- helpers ----------------
__device__ __forceinline__ uint32_t smem_u32(const void* p) {
    uint32_t a;
    asm("{ .reg .u64 t; cvta.to.shared.u64 t, %1; cvt.u32.u64 %0, t; }" : "=r"(a) : "l"(p));
    return a;
}
__device__ __forceinline__ float tf32r(float x) {
    uint32_t u;
    asm("cvt.rna.tf32.f32 %0, %1;" : "=r"(u) : "f"(x));
    return __uint_as_float(u);
}
__device__ __forceinline__ void mma_tf32(float d[4], const uint32_t a[4], const uint32_t b[2]) {
    asm volatile(
        "mma.sync.aligned.m16n8k8.row.col.f32.tf32.tf32.f32 "
        "{%0,%1,%2,%3}, {%4,%5,%6,%7}, {%8,%9}, {%0,%1,%2,%3};"
        : "+f"(d[0]), "+f"(d[1]), "+f"(d[2]), "+f"(d[3])
        : "r"(a[0]), "r"(a[1]), "r"(a[2]), "r"(a[3]), "r"(b[0]), "r"(b[1]));
}
__device__ __forceinline__ void cp_async8(uint32_t daddr, const void* gptr, uint32_t srcsz) {
    asm volatile("cp.async.ca.shared.global [%0], [%1], 8, %2;"
                 :: "r"(daddr), "l"(gptr), "r"(srcsz) : "memory");
}
#define CP_COMMIT() asm volatile("cp.async.commit_group;" ::: "memory")
#define CP_WAIT1()  asm volatile("cp.async.wait_group 1;" ::: "memory")

// ---------------- prep: zero counters + tf32-transpose all weights ----------------
__global__ void k_zero_trans(const float* __restrict__ W2, const float* __restrict__ W3,
                             const float* __restrict__ Wp, int N) {
    int i = blockIdx.x * blockDim.x + threadIdx.x;
    if (i < N) { g_degi[i] = 0; g_fill[i] = 0; }
    if (i < 2 * CMAX) g_stats[i] = 0.f;
    if (i < 128 * 256) {
        int k = i / 256, n = i % 256;
        g_Wt2[(size_t)n * 128 + k] = tf32r(W2[i]);
    }
    if (i < 256 * 256) {
        int k = i / 256, n = i % 256;
        g_Wt3[(size_t)n * 256 + k] = tf32r(W3[i]);
        g_Wtp[(size_t)n * 256 + k] = tf32r(Wp[i]);
    }
}
__global__ void k_deg_accum(const int* __restrict__ dst, int E) {
    int e = blockIdx.x * blockDim.x + threadIdx.x;
    if (e < E) atomicAdd(&g_degi[dst[e]], 1);
}
// scan level 1 + dis/selfn computation
__global__ void k_scan1(int N) {
    __shared__ int sh[256];
    int i = blockIdx.x * 256 + threadIdx.x;
    int v = (i < N) ? g_degi[i] : 0;
    if (i < N) {
        float d = (float)(v + 1);
        g_dis[i] = rsqrtf(d);
        g_selfn[i] = 1.0f / d;
    }
    sh[threadIdx.x] = v;
    __syncthreads();
    for (int off = 1; off < 256; off <<= 1) {
        int t = (threadIdx.x >= off) ? sh[threadIdx.x - off] : 0;
        __syncthreads();
        sh[threadIdx.x] += t;
        __syncthreads();
    }
    if (i < N) g_rowStart[i] = sh[threadIdx.x] - v;
    if (threadIdx.x == 255) g_blkSum[blockIdx.x] = sh[255];
}
__global__ void k_scan2(int NB) {
    __shared__ int sh[SCAN_NB];
    int v = ((int)threadIdx.x < NB) ? g_blkSum[threadIdx.x] : 0;
    sh[threadIdx.x] = v;
    __syncthreads();
    for (int off = 1; off < SCAN_NB; off <<= 1) {
        int t = ((int)threadIdx.x >= off) ? sh[threadIdx.x - off] : 0;
        __syncthreads();
        sh[threadIdx.x] += t;
        __syncthreads();
    }
    if ((int)threadIdx.x < NB) g_blkSum[threadIdx.x] = sh[threadIdx.x] - v;
}
__global__ void k_scan3(int N, int E) {
    int i = blockIdx.x * blockDim.x + threadIdx.x;
    if (i < N) g_rowStart[i] += g_blkSum[i >> 8];
    if (i == 0) g_rowStart[N] = E;
}
__global__ void k_csr_fill(const int* __restrict__ src, const int* __restrict__ dst, int E) {
    int e = blockIdx.x * blockDim.x + threadIdx.x;
    if (e < E) {
        int s = src[e], d = dst[e];
        int pos = g_rowStart[d] + atomicAdd(&g_fill[d], 1);
        g_csr_src[pos] = s;
        g_csr_w[pos]   = g_dis[s] * g_dis[d];
    }
}

// ---------------- fused layer-1: gather9 + GEMM[9->128] + stats ----------------
__global__ __launch_bounds__(256) void k_layer1(const float* __restrict__ x,
                                                const float* __restrict__ W1,
                                                float* __restrict__ Y, int N) {
    __shared__ float Ws[9 * 128];
    __shared__ float sstat[256];
    int tid = threadIdx.x;
    for (int i = tid; i < 9 * 128; i += 256) Ws[i] = W1[i];
    sstat[tid] = 0.f;
    __syncthreads();
    int wid = tid >> 5, lane = tid & 31;
    int i = blockIdx.x * 8 + wid;
    if (i < N) {
        float acc = 0.f;
        if (lane < 9) acc = g_selfn[i] * x[(size_t)i * 9 + lane];
        int st = g_rowStart[i], en = g_rowStart[i + 1];
        for (int j = st; j < en; j++) {
            int s = g_csr_src[j];
            float w = g_csr_w[j];
            if (lane < 9) acc += w * x[(size_t)s * 9 + lane];
        }
        float a[9];
#pragma unroll
        for (int k = 0; k < 9; k++) a[k] = __shfl_sync(0xFFFFFFFF, acc, k);
#pragma unroll
        for (int q = 0; q < 4; q++) {
            int c = q * 32 + lane;
            float y = 0.f;
#pragma unroll
            for (int k = 0; k < 9; k++) y += a[k] * Ws[k * 128 + c];
            Y[(size_t)i * 128 + c] = y;
            atomicAdd(&sstat[c], y);
            atomicAdd(&sstat[128 + c], y * y);
        }
    }
    __syncthreads();
    if (tid < 128) {
        atomicAdd(&g_stats[tid], sstat[tid]);
        atomicAdd(&g_stats[256 + tid], sstat[128 + tid]);
    }
}

// ---------------- BN finalize (resets stats for next layer) ----------------
__global__ void k_finalize(const float* __restrict__ gamma,
                           const float* __restrict__ beta, int N, int C) {
    int c = threadIdx.x;
    if (c < C) {
        float invN = 1.0f / (float)N;
        float mean = g_stats[c] * invN;
        float var  = g_stats[256 + c] * invN - mean * mean;
        float sc   = gamma[c] * rsqrtf(var + 1e-5f);
        g_scale[c] = sc;
        g_shift[c] = beta[c] - mean * sc;
        g_stats[c] = 0.f;
        g_stats[256 + c] = 0.f;
    }
}

// ---------------- gather + fused BN+ReLU: 8 channels/thread, edge prefetch ----------------
// TPN = C/8 threads per node; NPB = 256/TPN nodes per block.
template <int C>
__global__ __launch_bounds__(256) void k_gather_bn8(const float* __restrict__ Y,
                                                    float* __restrict__ P, int N) {
    constexpr int TPN = C / 8;
    constexpr int NPB = 256 / TPN;
    const int sub = threadIdx.x / TPN;
    const int cq  = threadIdx.x % TPN;          // owns channels [cq*8, cq*8+8)
    const int i   = blockIdx.x * NPB + sub;
    if (i >= N) return;
    const float4 sc0 = ((const float4*)g_scale)[cq * 2];
    const float4 sc1 = ((const float4*)g_scale)[cq * 2 + 1];
    const float4 sh0 = ((const float4*)g_shift)[cq * 2];
    const float4 sh1 = ((const float4*)g_shift)[cq * 2 + 1];
    const float4* Yv = (const float4*)Y;
    const int stride4 = C / 4;

    float w0 = g_selfn[i];
    float4 y0 = Yv[(size_t)i * stride4 + cq * 2];
    float4 y1 = Yv[(size_t)i * stride4 + cq * 2 + 1];
    float4 a0, a1;
    a0.x = w0 * fmaxf(0.f, y0.x * sc0.x + sh0.x);
    a0.y = w0 * fmaxf(0.f, y0.y * sc0.y + sh0.y);
    a0.z = w0 * fmaxf(0.f, y0.z * sc0.z + sh0.z);
    a0.w = w0 * fmaxf(0.f, y0.w * sc0.w + sh0.w);
    a1.x = w0 * fmaxf(0.f, y1.x * sc1.x + sh1.x);
    a1.y = w0 * fmaxf(0.f, y1.y * sc1.y + sh1.y);
    a1.z = w0 * fmaxf(0.f, y1.z * sc1.z + sh1.z);
    a1.w = w0 * fmaxf(0.f, y1.w * sc1.w + sh1.w);

    const int st = g_rowStart[i], en = g_rowStart[i + 1];
    int   s_nx = 0;
    float w_nx = 0.f;
    if (st < en) { s_nx = g_csr_src[st]; w_nx = g_csr_w[st]; }
    for (int j = st; j < en; j++) {
        int s = s_nx;
        float w = w_nx;
        if (j + 1 < en) { s_nx = g_csr_src[j + 1]; w_nx = g_csr_w[j + 1]; }
        float4 v0 = Yv[(size_t)s * stride4 + cq * 2];
        float4 v1 = Yv[(size_t)s * stride4 + cq * 2 + 1];
        a0.x += w * fmaxf(0.f, v0.x * sc0.x + sh0.x);
        a0.y += w * fmaxf(0.f, v0.y * sc0.y + sh0.y);
        a0.z += w * fmaxf(0.f, v0.z * sc0.z + sh0.z);
        a0.w += w * fmaxf(0.f, v0.w * sc0.w + sh0.w);
        a1.x += w * fmaxf(0.f, v1.x * sc1.x + sh1.x);
        a1.y += w * fmaxf(0.f, v1.y * sc1.y + sh1.y);
        a1.z += w * fmaxf(0.f, v1.z * sc1.z + sh1.z);
        a1.w += w * fmaxf(0.f, v1.w * sc1.w + sh1.w);
    }
    ((float4*)P)[(size_t)i * stride4 + cq * 2] =
        make_float4(tf32r(a0.x), tf32r(a0.y), tf32r(a0.z), tf32r(a0.w));
    ((float4*)P)[(size_t)i * stride4 + cq * 2 + 1] =
        make_float4(tf32r(a1.x), tf32r(a1.y), tf32r(a1.z), tf32r(a1.w));
}

// ---------------- tf32 mma GEMM, cp.async double-buffered, fused stats ----------------
__global__ __launch_bounds__(256, 2) void k_mma(const float* __restrict__ A,
                                                const float* __restrict__ Wt,
                                                float* __restrict__ C,
                                                int M, int K,
                                                const float* __restrict__ bias,
                                                int doStats) {
    extern __shared__ __align__(16) float sm[];
    const int tid  = threadIdx.x;
    const int wid  = tid >> 5;
    const int lane = tid & 31;
    const int wr   = (wid & 1) * 64;
    const int wc   = (wid >> 1) * 32;
    const int row0 = blockIdx.y * 128;
    const int col0 = blockIdx.x * 128;
    const int gq   = lane >> 2;
    const int tq   = lane & 3;
    const uint32_t sbase = smem_u32(sm);
    const int nk = K >> 5;

    float acc[4][4][4];
#pragma unroll
    for (int mt = 0; mt < 4; mt++)
#pragma unroll
        for (int nt = 0; nt < 4; nt++)
#pragma unroll
            for (int q = 0; q < 4; q++) acc[mt][nt][q] = 0.f;

    auto load_stage = [&](int s, int k0) {
#pragma unroll
        for (int i = 0; i < 8; i++) {
            int idx = tid + i * 256;
            int r = idx >> 4, j2 = idx & 15;
            int gr = row0 + r;
            uint32_t da = sbase + (uint32_t)(s * 4608 + r * 36 + j2 * 2) * 4;
            cp_async8(da, A + (size_t)gr * K + k0 + j2 * 2, (gr < M) ? 8u : 0u);
        }
#pragma unroll
        for (int i = 0; i < 8; i++) {
            int idx = tid + i * 256;
            int n = idx >> 4, j2 = idx & 15;
            uint32_t db = sbase + (uint32_t)(9216 + s * 4608 + n * 36 + j2 * 2) * 4;
            cp_async8(db, Wt + (size_t)(col0 + n) * K + k0 + j2 * 2, 8u);
        }
    };

    load_stage(0, 0);
    CP_COMMIT();
    for (int kt = 0; kt < nk; kt++) {
        if (kt + 1 < nk) load_stage((kt + 1) & 1, (kt + 1) * 32);
        CP_COMMIT();
        CP_WAIT1();
        __syncthreads();
        const float* As = sm + (kt & 1) * 4608;
        const float* Bs = sm + 9216 + (kt & 1) * 4608;
#pragma unroll
        for (int kk = 0; kk < 4; kk++) {
            uint32_t af[4][4], bf[4][2];
#pragma unroll
            for (int mt = 0; mt < 4; mt++) {
                int r = wr + mt * 16 + gq;
                af[mt][0] = __float_as_uint(As[r * 36 + kk * 8 + tq]);
                af[mt][1] = __float_as_uint(As[(r + 8) * 36 + kk * 8 + tq]);
                af[mt][2] = __float_as_uint(As[r * 36 + kk * 8 + 4 + tq]);
                af[mt][3] = __float_as_uint(As[(r + 8) * 36 + kk * 8 + 4 + tq]);
            }
#pragma unroll
            for (int nt = 0; nt < 4; nt++) {
                int n = wc + nt * 8 + gq;
                bf[nt][0] = __float_as_uint(Bs[n * 36 + kk * 8 + tq]);
                bf[nt][1] = __float_as_uint(Bs[n * 36 + kk * 8 + 4 + tq]);
            }
#pragma unroll
            for (int mt = 0; mt < 4; mt++)
#pragma unroll
                for (int nt = 0; nt < 4; nt++)
                    mma_tf32(acc[mt][nt], af[mt], bf[nt]);
        }
        __syncthreads();
    }

#pragma unroll
    for (int mt = 0; mt < 4; mt++) {
        int r0 = row0 + wr + mt * 16 + gq;
        int r1 = r0 + 8;
#pragma unroll
        for (int nt = 0; nt < 4; nt++) {
            int c = col0 + wc + nt * 8 + tq * 2;
            float b0 = 0.f, b1 = 0.f;
            if (bias) { b0 = bias[c]; b1 = bias[c + 1]; }
            if (r0 < M)
                *(float2*)(C + (size_t)r0 * 256 + c) =
                    make_float2(acc[mt][nt][0] + b0, acc[mt][nt][1] + b1);
            if (r1 < M)
                *(float2*)(C + (size_t)r1 * 256 + c) =
                    make_float2(acc[mt][nt][2] + b0, acc[mt][nt][3] + b1);
        }
    }

    if (doStats) {
#pragma unroll
        for (int nt = 0; nt < 4; nt++) {
#pragma unroll
            for (int q = 0; q < 2; q++) {
                float s = 0.f, sq = 0.f;
#pragma unroll
                for (int mt = 0; mt < 4; mt++) {
                    float a = acc[mt][nt][q], b = acc[mt][nt][q + 2];
                    s += a + b;
                    sq += a * a + b * b;
                }
#pragma unroll
                for (int off = 4; off < 32; off <<= 1) {
                    s  += __shfl_xor_sync(0xFFFFFFFF, s, off);
                    sq += __shfl_xor_sync(0xFFFFFFFF, sq, off);
                }
                if (gq == 0) {
                    int c = col0 + wc + nt * 8 + tq * 2 + q;
                    atomicAdd(&g_stats[c], s);
                    atomicAdd(&g_stats[256 + c], sq);
                }
            }
        }
    }
}

// ---------------- pool with fused BN+ReLU (batch sorted) ----------------
__global__ void k_pool(const float* __restrict__ Y, const int* __restrict__ batch,
                       int N, int G) {
    int g = blockIdx.x;
    int c = threadIdx.x;
    __shared__ int s_lo, s_hi;
    if (c == 0) {
        int lo = 0, hi = N;
        while (lo < hi) { int m = (lo + hi) >> 1; if (batch[m] < g) lo = m + 1; else hi = m; }
        s_lo = lo;
        int lo2 = lo, hi2 = N;
        while (lo2 < hi2) { int m = (lo2 + hi2) >> 1; if (batch[m] <= g) lo2 = m + 1; else hi2 = m; }
        s_hi = lo2;
    }
    __syncthreads();
    float sc = g_scale[c], sh = g_shift[c];
    float sum = 0.f;
    for (int i = s_lo; i < s_hi; i++)
        sum += fmaxf(0.f, Y[(size_t)i * 256 + c] * sc + sh);
    int cnt = s_hi - s_lo;
    g_pooled[(size_t)g * 256 + c] = tf32r(sum / fmaxf((float)cnt, 1.0f));
}

// ---------------- host launcher ----------------
extern "C" void kernel_launch(void* const* d_in, const int* in_sizes, int n_in,
                              void* d_out, int out_size) {
    const float* x     = (const float*)d_in[0];
    const int*   ei    = (const int*)d_in[1];
    const int*   batch = (const int*)d_in[2];
    const float* W1  = (const float*)d_in[4];
    const float* g1  = (const float*)d_in[6];
    const float* be1 = (const float*)d_in[7];
    const float* W2  = (const float*)d_in[8];
    const float* g2  = (const float*)d_in[10];
    const float* be2 = (const float*)d_in[11];
    const float* W3  = (const float*)d_in[12];
    const float* g3  = (const float*)d_in[14];
    const float* be3 = (const float*)d_in[15];
    const float* Wp  = (const float*)d_in[16];
    const float* bp  = (const float*)d_in[17];
    float* out = (float*)d_out;

    const int N = in_sizes[0] / 9;
    const int E = in_sizes[1] / 2;
    const int G = out_size / 256;
    const int NB = (N + 255) / 256;
    const int SMEM_MMA = 4 * 4608 * 4;

    cudaFuncSetAttribute(k_mma, cudaFuncAttributeMaxDynamicSharedMemorySize, SMEM_MMA);

    void *pA, *pB, *pPooled, *pWt2, *pWt3, *pWtp;
    cudaGetSymbolAddress(&pA, g_bufA);
    cudaGetSymbolAddress(&pB, g_bufB);
    cudaGetSymbolAddress(&pPooled, g_pooled);
    cudaGetSymbolAddress(&pWt2, g_Wt2);
    cudaGetSymbolAddress(&pWt3, g_Wt3);
    cudaGetSymbolAddress(&pWtp, g_Wtp);
    float* bufA = (float*)pA;
    float* bufB = (float*)pB;

    const int* src = ei;
    const int* dst = ei + E;

    // ---- prep ----
    k_zero_trans<<<NB, 256>>>(W2, W3, Wp, N);
    k_deg_accum<<<(E + 255) / 256, 256>>>(dst, E);
    k_scan1<<<NB, 256>>>(N);
    k_scan2<<<1, SCAN_NB>>>(NB);
    k_scan3<<<NB, 256>>>(N, E);
    k_csr_fill<<<(E + 255) / 256, 256>>>(src, dst, E);

    // ---- Layer 1 (fused gather + GEMM + stats) ----
    k_layer1<<<(N + 7) / 8, 256>>>(x, W1, bufB, N);
    k_finalize<<<1, 128>>>(g1, be1, N, 128);

    // ---- Layer 2 ----
    k_gather_bn8<128><<<(N + 15) / 16, 256>>>(bufB, bufA, N);
    {
        dim3 grid(2, (N + 127) / 128);
        k_mma<<<grid, 256, SMEM_MMA>>>(bufA, (const float*)pWt2, bufB, N, 128, nullptr, 1);
    }
    k_finalize<<<1, 256>>>(g2, be2, N, 256);

    // ---- Layer 3 ----
    k_gather_bn8<256><<<(N + 7) / 8, 256>>>(bufB, bufA, N);
    {
        dim3 grid(2, (N + 127) / 128);
        k_mma<<<grid, 256, SMEM_MMA>>>(bufA, (const float*)pWt3, bufB, N, 256, nullptr, 1);
    }
    k_finalize<<<1, 256>>>(g3, be3, N, 256);

    // ---- pool + final linear ----
    k_pool<<<G, 256>>>(bufB, batch, N, G);
    {
        dim3 grid(2, (G + 127) / 128);
        k_mma<<<grid, 256, SMEM_MMA>>>((const float*)pPooled, (const float*)pWtp, out,
                                       G, 256, bp, 0);
    }
}